// round 7
// baseline (speedup 1.0000x reference)
#include <cuda_runtime.h>
#include <math.h>

#define NNODE 94
#define MAXB  16384
#define NOUT  6400

typedef unsigned long long u64;

// Scratch (device globals — no allocation allowed in kernel_launch)
__device__ float g_A  [NNODE * NNODE];   // dense normalized adjacency, A[dst][src]
__device__ float g_Ht [NNODE * MAXB];    // H transposed: g_Ht[k*B + b]
__device__ float g_WT [NNODE * NOUT];    // Wfc transposed: g_WT[k*6400 + n]

// ---------------------------------------------------------------------------
// Packed f32x2 helpers (sm_100+): 2 FMAs per issue slot — the only way past
// the FFMA-3reg rt_SMSP=2 structural ceiling.
// ---------------------------------------------------------------------------
__device__ __forceinline__ u64 fma2(u64 a, u64 b, u64 c) {
    u64 d;
    asm("fma.rn.f32x2 %0, %1, %2, %3;" : "=l"(d) : "l"(a), "l"(b), "l"(c));
    return d;
}
__device__ __forceinline__ u64 add2(u64 a, u64 b) {
    u64 d;
    asm("add.rn.f32x2 %0, %1, %2;" : "=l"(d) : "l"(a), "l"(b));
    return d;
}
__device__ __forceinline__ u64 pack2(float x) {
    u64 d;
    asm("mov.b64 %0, {%1, %1};" : "=l"(d) : "r"(__float_as_uint(x)));
    return d;
}

// ---------------------------------------------------------------------------
// Kernel 1: build dense normalized adjacency (single block)
// ---------------------------------------------------------------------------
__global__ void build_graph_kernel(const int* __restrict__ ei,
                                   const float* __restrict__ ew, int E) {
    __shared__ float deg[NNODE];
    __shared__ float dinv[NNODE];
    int t = threadIdx.x;
    for (int i = t; i < NNODE; i += blockDim.x) deg[i] = 1.0f;  // self loop
    __syncthreads();
    for (int e = t; e < E; e += blockDim.x)
        atomicAdd(&deg[ei[E + e]], ew[e]);
    __syncthreads();
    for (int i = t; i < NNODE; i += blockDim.x)
        dinv[i] = (deg[i] > 0.0f) ? rsqrtf(deg[i]) : 0.0f;
    for (int i = t; i < NNODE * NNODE; i += blockDim.x) g_A[i] = 0.0f;
    __syncthreads();
    for (int e = t; e < E; e += blockDim.x) {
        int s = ei[e];
        int d = ei[E + e];
        atomicAdd(&g_A[d * NNODE + s], dinv[s] * ew[e] * dinv[d]);
    }
    for (int i = t; i < NNODE; i += blockDim.x)
        atomicAdd(&g_A[i * NNODE + i], dinv[i] * dinv[i]);
}

// ---------------------------------------------------------------------------
// Kernel 2: transpose Wfc [6400,94] -> g_WT [94,6400]
// ---------------------------------------------------------------------------
__global__ void transpose_w_kernel(const float* __restrict__ Wfc) {
    int idx = blockIdx.x * blockDim.x + threadIdx.x;
    if (idx < NOUT * NNODE) {
        int n = idx / NNODE;
        int k = idx - n * NNODE;
        g_WT[k * NOUT + n] = Wfc[idx];
    }
}

// ---------------------------------------------------------------------------
// Kernel 3: GCN stage, 2 batch elements per block concurrently (y dim),
// A transposed + padded to 96 in smem for conflict-free LDS.
// ---------------------------------------------------------------------------
#define S1Y 2

__global__ void __launch_bounds__(96 * S1Y)
stage1_kernel(const float* __restrict__ feat,
              const float* __restrict__ W1,
              const float* __restrict__ b1,
              const float* __restrict__ W2,
              const float* __restrict__ b2,
              int B, int bpb) {
    __shared__ float AsT[NNODE * 96];          // AsT[j*96 + t] = A[t][j]
    __shared__ float xw[S1Y][6][NNODE];
    __shared__ float h1v[S1Y][NNODE];
    __shared__ float fbuf[S1Y][NNODE * 3];
    __shared__ float w1s[18], b1s[6], w2s[6], b2s[1];

    const int t   = threadIdx.x;               // 0..95
    const int y   = threadIdx.y;               // 0..S1Y-1
    const int tid = y * 96 + t;
    const int nth = 96 * S1Y;

    for (int i = tid; i < NNODE * NNODE; i += nth) {
        int r = i / NNODE;
        int j = i - r * NNODE;
        AsT[j * 96 + r] = g_A[i];
    }
    if (tid < 18) w1s[tid] = W1[tid];
    if (tid < 6)  { b1s[tid] = b1[tid]; w2s[tid] = W2[tid]; }
    if (tid == 0) b2s[0] = b2[0];
    __syncthreads();

    for (int bb = 0; bb < bpb; bb += S1Y) {
        const int b = blockIdx.x * bpb + bb + y;
        const bool act = (b < B);

        if (act)
            for (int i = t; i < NNODE * 3; i += 96)
                fbuf[y][i] = feat[b * (NNODE * 3) + i];
        __syncthreads();

        if (act && t < NNODE) {
            float x0 = fbuf[y][t * 3 + 0];
            float x1 = fbuf[y][t * 3 + 1];
            float x2 = fbuf[y][t * 3 + 2];
            #pragma unroll
            for (int c = 0; c < 6; c++)
                xw[y][c][t] = x0 * w1s[c] + x1 * w1s[6 + c] + x2 * w1s[12 + c];
        }
        __syncthreads();

        if (act && t < NNODE) {
            float acc[6] = {0, 0, 0, 0, 0, 0};
            #pragma unroll 2
            for (int j = 0; j < NNODE; j++) {
                float a = AsT[j * 96 + t];
                #pragma unroll
                for (int c = 0; c < 6; c++) acc[c] += a * xw[y][c][j];
            }
            float hz = 0.0f;
            #pragma unroll
            for (int c = 0; c < 6; c++)
                hz += tanhf(acc[c] + b1s[c]) * w2s[c];
            h1v[y][t] = hz;
        }
        __syncthreads();

        if (act && t < NNODE) {
            float a0 = 0.0f, a1 = 0.0f;
            #pragma unroll 2
            for (int j = 0; j < NNODE; j += 2) {
                a0 += AsT[j * 96 + t]       * h1v[y][j];
                a1 += AsT[(j + 1) * 96 + t] * h1v[y][j + 1];
            }
            g_Ht[t * B + b] = tanhf(a0 + a1 + b2s[0]);
        }
        __syncthreads();
    }
}

// ---------------------------------------------------------------------------
// Kernel 4: FC GEMM with packed f32x2 FMAs.
// out[m][n] = sum_k Ht[k][m] * WT[k][n] + bfc[n]
// 128x128 tile, BK=96, 8x8 per thread (4+4 split), acc as 32 packed f32x2.
// ---------------------------------------------------------------------------
#define BM 128
#define BN 128
#define BK 96

__global__ void __launch_bounds__(256, 2)
fc_gemm_kernel(const float* __restrict__ bfc, float* __restrict__ out, int B) {
    extern __shared__ float sm[];
    float* Hs = sm;             // [BK][BM]
    float* Ws = sm + BK * BM;   // [BK][BN]

    const int tid = threadIdx.x;
    const int m0 = blockIdx.y * BM;
    const int n0 = blockIdx.x * BN;

    for (int i = tid; i < BK * BM; i += 256) {
        int k = i >> 7, m = i & 127;
        Hs[i] = (k < NNODE && (m0 + m) < B) ? g_Ht[k * B + m0 + m] : 0.0f;
    }
    for (int i = tid; i < BK * BN; i += 256) {
        int k = i >> 7, n = i & 127;
        Ws[i] = (k < NNODE) ? g_WT[k * NOUT + n0 + n] : 0.0f;
    }
    __syncthreads();

    const int tm = (tid & 15) * 4;   // m fragment base (and +64)
    const int tn = (tid >> 4) * 4;   // n fragment base (and +64)

    // acc2[i][jp]: m row i (4+4 split), n pair jp (jp<2: tn+2jp, jp>=2: 64+tn+2(jp-2))
    u64 acc2[8][4];
    #pragma unroll
    for (int i = 0; i < 8; i++)
        #pragma unroll
        for (int jp = 0; jp < 4; jp++) acc2[i][jp] = 0ull;

    #pragma unroll 4
    for (int k = 0; k < BK; k++) {
        float4 a0 = *(const float4*)(Hs + k * BM + tm);
        float4 a1 = *(const float4*)(Hs + k * BM + 64 + tm);
        ulonglong2 b0 = *(const ulonglong2*)(Ws + k * BN + tn);
        ulonglong2 b1 = *(const ulonglong2*)(Ws + k * BN + 64 + tn);
        u64 bv[4] = {b0.x, b0.y, b1.x, b1.y};
        float av[8] = {a0.x, a0.y, a0.z, a0.w, a1.x, a1.y, a1.z, a1.w};
        #pragma unroll
        for (int i = 0; i < 8; i++) {
            u64 ai = pack2(av[i]);
            #pragma unroll
            for (int jp = 0; jp < 4; jp++)
                acc2[i][jp] = fma2(ai, bv[jp], acc2[i][jp]);
        }
    }

    // Bias as packed pairs (bfc rows are 16B-aligned at tn multiples of 4)
    ulonglong2 bb0 = *(const ulonglong2*)(bfc + n0 + tn);
    ulonglong2 bb1 = *(const ulonglong2*)(bfc + n0 + 64 + tn);
    u64 bp[4] = {bb0.x, bb0.y, bb1.x, bb1.y};

    #pragma unroll
    for (int i = 0; i < 8; i++) {
        int m = m0 + ((i < 4) ? (tm + i) : (64 + tm + i - 4));
        if (m >= B) continue;
        ulonglong2 o0, o1;
        o0.x = add2(acc2[i][0], bp[0]);
        o0.y = add2(acc2[i][1], bp[1]);
        o1.x = add2(acc2[i][2], bp[2]);
        o1.y = add2(acc2[i][3], bp[3]);
        *(ulonglong2*)(out + (size_t)m * NOUT + n0 + tn)      = o0;
        *(ulonglong2*)(out + (size_t)m * NOUT + n0 + 64 + tn) = o1;
    }
}

// ---------------------------------------------------------------------------
// Launch
// ---------------------------------------------------------------------------
extern "C" void kernel_launch(void* const* d_in, const int* in_sizes, int n_in,
                              void* d_out, int out_size) {
    const float* feature = (const float*)d_in[0];
    const int*   ei      = (const int*)  d_in[1];
    const float* ew      = (const float*)d_in[2];
    const float* W1      = (const float*)d_in[3];
    const float* b1      = (const float*)d_in[4];
    const float* W2      = (const float*)d_in[5];
    const float* b2      = (const float*)d_in[6];
    const float* Wfc     = (const float*)d_in[7];
    const float* bfc     = (const float*)d_in[8];
    float*       out     = (float*)d_out;

    const int B = in_sizes[0] / (NNODE * 3);
    const int E = in_sizes[1] / 2;

    build_graph_kernel<<<1, 256>>>(ei, ew, E);
    transpose_w_kernel<<<(NOUT * NNODE + 255) / 256, 256>>>(Wfc);

    const int grid1 = 1024;
    const int bpb = (B + grid1 - 1) / grid1;   // 16 when B=16384
    dim3 s1block(96, S1Y);
    stage1_kernel<<<grid1, s1block>>>(feature, W1, b1, W2, b2, B, bpb);

    cudaFuncSetAttribute(fc_gemm_kernel,
                         cudaFuncAttributeMaxDynamicSharedMemorySize,
                         2 * BK * BM * (int)sizeof(float));
    dim3 grid(NOUT / BN, (B + BM - 1) / BM);
    fc_gemm_kernel<<<grid, 256, 2 * BK * BM * sizeof(float)>>>(bfc, out, B);
}

// round 11
// speedup vs baseline: 1.4926x; 1.4926x over previous
#include <cuda_runtime.h>
#include <cuda_bf16.h>
#include <math.h>

#define NNODE 94
#define MAXB  16384
#define NOUT  6400
#define KP    96          // K padded
#define NS    (KP / 16)   // 6 k-steps

typedef unsigned long long u64;
typedef unsigned int u32;
typedef unsigned short u16;

// Scratch (device globals — no allocation allowed)
__device__ float          g_A  [NNODE * NNODE];     // dense normalized adjacency
__device__ __nv_bfloat16  g_Ahi[MAXB * KP];         // H hi, [m][KP]
__device__ __nv_bfloat16  g_Alo[MAXB * KP];         // H lo
__device__ __nv_bfloat16  g_Bhi[NOUT * KP];         // Wfc hi, [n][KP]
__device__ __nv_bfloat16  g_Blo[NOUT * KP];         // Wfc lo

// ===========================================================================
// bf16 mma.sync wrapper (baseline ISA, works on plain sm_103 target)
// ===========================================================================
__device__ __forceinline__ void mma_bf16(float& d0, float& d1, float& d2, float& d3,
                                         u32 a0, u32 a1, u32 a2, u32 a3,
                                         u32 b0, u32 b1) {
    asm volatile(
        "mma.sync.aligned.m16n8k16.row.col.f32.bf16.bf16.f32 "
        "{%0,%1,%2,%3}, {%4,%5,%6,%7}, {%8,%9}, {%0,%1,%2,%3};"
        : "+f"(d0), "+f"(d1), "+f"(d2), "+f"(d3)
        : "r"(a0), "r"(a1), "r"(a2), "r"(a3), "r"(b0), "r"(b1));
}

// ===========================================================================
// Kernel 1: build dense normalized adjacency (single block)
// ===========================================================================
__global__ void build_graph_kernel(const int* __restrict__ ei,
                                   const float* __restrict__ ew, int E) {
    __shared__ float deg[NNODE];
    __shared__ float dinv[NNODE];
    int t = threadIdx.x;
    for (int i = t; i < NNODE; i += blockDim.x) deg[i] = 1.0f;
    __syncthreads();
    for (int e = t; e < E; e += blockDim.x)
        atomicAdd(&deg[ei[E + e]], ew[e]);
    __syncthreads();
    for (int i = t; i < NNODE; i += blockDim.x)
        dinv[i] = (deg[i] > 0.0f) ? rsqrtf(deg[i]) : 0.0f;
    for (int i = t; i < NNODE * NNODE; i += blockDim.x) g_A[i] = 0.0f;
    __syncthreads();
    for (int e = t; e < E; e += blockDim.x) {
        int s = ei[e];
        int d = ei[E + e];
        atomicAdd(&g_A[d * NNODE + s], dinv[s] * ew[e] * dinv[d]);
    }
    for (int i = t; i < NNODE; i += blockDim.x)
        atomicAdd(&g_A[i * NNODE + i], dinv[i] * dinv[i]);
}

// ===========================================================================
// Kernel 2: convert Wfc [6400][94] -> hi/lo bf16 [6400][96] (pad zero)
// ===========================================================================
__global__ void convert_w_kernel(const float* __restrict__ Wfc) {
    int idx = blockIdx.x * blockDim.x + threadIdx.x;
    if (idx >= NOUT * KP) return;
    int n = idx / KP, k = idx - n * KP;
    float f = (k < NNODE) ? Wfc[n * NNODE + k] : 0.0f;
    __nv_bfloat16 h = __float2bfloat16_rn(f);
    g_Bhi[idx] = h;
    g_Blo[idx] = __float2bfloat16_rn(f - __bfloat162float(h));
}

// ===========================================================================
// Kernel 3: GCN stage (R<=6 winning variant), emits hi/lo bf16 [m][96]
// ===========================================================================
__global__ void stage1_kernel(const float* __restrict__ feat,
                              const float* __restrict__ W1,
                              const float* __restrict__ b1,
                              const float* __restrict__ W2,
                              const float* __restrict__ b2,
                              int B, int bpb) {
    __shared__ float As[NNODE * NNODE];
    __shared__ float xw[6][NNODE];
    __shared__ float h1v[NNODE];
    __shared__ float fbuf[NNODE * 3];
    __shared__ float w1s[18], b1s[6], w2s[6], b2s;

    int t = threadIdx.x;
    for (int i = t; i < NNODE * NNODE; i += blockDim.x) As[i] = g_A[i];
    if (t < 18) w1s[t] = W1[t];
    if (t < 6)  { b1s[t] = b1[t]; w2s[t] = W2[t]; }
    if (t == 0) b2s = b2[0];
    __syncthreads();

    for (int bb = 0; bb < bpb; bb++) {
        int b = blockIdx.x * bpb + bb;
        if (b >= B) return;

        for (int i = t; i < NNODE * 3; i += blockDim.x)
            fbuf[i] = feat[b * (NNODE * 3) + i];
        __syncthreads();

        if (t < NNODE) {
            float x0 = fbuf[t * 3 + 0], x1 = fbuf[t * 3 + 1], x2 = fbuf[t * 3 + 2];
            #pragma unroll
            for (int c = 0; c < 6; c++)
                xw[c][t] = x0 * w1s[c] + x1 * w1s[6 + c] + x2 * w1s[12 + c];
        }
        __syncthreads();

        float hz = 0.0f;
        if (t < NNODE) {
            float acc[6] = {0, 0, 0, 0, 0, 0};
            for (int j = 0; j < NNODE; j++) {
                float a = As[t * NNODE + j];
                #pragma unroll
                for (int c = 0; c < 6; c++) acc[c] += a * xw[c][j];
            }
            #pragma unroll
            for (int c = 0; c < 6; c++)
                hz += tanhf(acc[c] + b1s[c]) * w2s[c];
        }
        __syncthreads();
        if (t < NNODE) h1v[t] = hz;
        __syncthreads();

        if (t < KP) {
            float v = 0.0f;
            if (t < NNODE) {
                float acc = 0.0f;
                for (int j = 0; j < NNODE; j++) acc += As[t * NNODE + j] * h1v[j];
                v = tanhf(acc + b2s);
            }
            __nv_bfloat16 h = __float2bfloat16_rn(v);
            g_Ahi[b * KP + t] = h;
            g_Alo[b * KP + t] = __float2bfloat16_rn(v - __bfloat162float(h));
        }
        __syncthreads();
    }
}

// ===========================================================================
// Kernel 4: FC GEMM via mma.sync bf16, hi/lo 3-product split.
// out[m][n] = sum_k H[m][k] * Wfc[n][k] + bfc[n]
// 128x128 tile, full K=96. Fragment-packed smem (conflict-free LDS.128).
//
// Fragment record layouts (one uint4 = 16B per lane):
//   A record (mf, s, rec, lane): lane -> g=lane/4, t=lane%4
//     m = m0 + mf*16 + rec*8 + g
//     {hi(k=16s+2t,+1), hi(k+8,+9), lo(..), lo(..)}  (rec0 -> a0/a2, rec1 -> a1/a3)
//   B record (nf, s, lane): n = n0 + nf*8 + g
//     {hi b0(k01), hi b1(k89), lo b0, lo b1}
// ===========================================================================
#define A_RECS (8 * NS * 2 * 32)   // 3072
#define B_RECS (16 * NS * 32)      // 3072
#define FC_SMEM ((A_RECS + B_RECS) * 16)  // 98304 bytes

__global__ void __launch_bounds__(256, 2)
fc_mma_kernel(const float* __restrict__ bfc, float* __restrict__ out, int B) {
    extern __shared__ char sm[];
    uint4* Af = (uint4*)sm;             // A_RECS records
    uint4* Bf = (uint4*)sm + A_RECS;    // B_RECS records

    const int tid  = threadIdx.x;
    const int wid  = tid >> 5;
    const int lane = tid & 31;
    const int m0   = blockIdx.y * 128;
    const int n0   = blockIdx.x * 128;

    // ---- Stage A fragments ----
    for (int r = tid; r < A_RECS; r += 256) {
        int l  = r & 31;
        int rc = (r >> 5) & 1;
        int s  = (r >> 6) % NS;
        int mf = r / (NS * 2 * 32);
        int g = l >> 2, t = l & 3;
        int m = m0 + mf * 16 + rc * 8 + g;
        uint4 v = make_uint4(0, 0, 0, 0);
        if (m < B) {
            const u16* ph = (const u16*)g_Ahi + m * KP + s * 16 + 2 * t;
            const u16* pl = (const u16*)g_Alo + m * KP + s * 16 + 2 * t;
            v.x = *(const u32*)ph;
            v.y = *(const u32*)(ph + 8);
            v.z = *(const u32*)pl;
            v.w = *(const u32*)(pl + 8);
        }
        Af[r] = v;
    }
    // ---- Stage B fragments ----
    for (int r = tid; r < B_RECS; r += 256) {
        int l  = r & 31;
        int s  = (r >> 5) % NS;
        int nf = r / (NS * 32);
        int g = l >> 2, t = l & 3;
        int n = n0 + nf * 8 + g;
        const u16* ph = (const u16*)g_Bhi + n * KP + s * 16 + 2 * t;
        const u16* pl = (const u16*)g_Blo + n * KP + s * 16 + 2 * t;
        uint4 v;
        v.x = *(const u32*)ph;
        v.y = *(const u32*)(ph + 8);
        v.z = *(const u32*)pl;
        v.w = *(const u32*)(pl + 8);
        Bf[r] = v;
    }
    __syncthreads();

    // Warp tiling: 4 (m) x 2 (n) warps; warp tile = m32 x n64
    const int wm = wid & 3;          // m warp
    const int wn = wid >> 2;         // n warp
    const int mf0 = wm * 2;          // 2 m-frags of 16
    const int nf0 = wn * 8;          // 8 n-frags of 8

    float acc[2][8][4];
    #pragma unroll
    for (int i = 0; i < 2; i++)
        #pragma unroll
        for (int j = 0; j < 8; j++)
            #pragma unroll
            for (int c = 0; c < 4; c++) acc[i][j][c] = 0.0f;

    #pragma unroll
    for (int s = 0; s < NS; s++) {
        uint4 ar0[2], ar1[2];
        #pragma unroll
        for (int i = 0; i < 2; i++) {
            int mf = mf0 + i;
            ar0[i] = Af[((mf * NS + s) * 2 + 0) * 32 + lane];
            ar1[i] = Af[((mf * NS + s) * 2 + 1) * 32 + lane];
        }
        #pragma unroll
        for (int j = 0; j < 8; j++) {
            uint4 br = Bf[((nf0 + j) * NS + s) * 32 + lane];
            #pragma unroll
            for (int i = 0; i < 2; i++) {
                // hi * hi
                mma_bf16(acc[i][j][0], acc[i][j][1], acc[i][j][2], acc[i][j][3],
                         ar0[i].x, ar1[i].x, ar0[i].y, ar1[i].y, br.x, br.y);
                // hi * lo
                mma_bf16(acc[i][j][0], acc[i][j][1], acc[i][j][2], acc[i][j][3],
                         ar0[i].x, ar1[i].x, ar0[i].y, ar1[i].y, br.z, br.w);
                // lo * hi
                mma_bf16(acc[i][j][0], acc[i][j][1], acc[i][j][2], acc[i][j][3],
                         ar0[i].z, ar1[i].z, ar0[i].w, ar1[i].w, br.x, br.y);
            }
        }
    }

    // ---- Epilogue: D[g][2t..], D[g+8][2t..] per frag; add bias; store ----
    const int g = lane >> 2, t = lane & 3;
    #pragma unroll
    for (int j = 0; j < 8; j++) {
        int n_col = n0 + (nf0 + j) * 8 + 2 * t;
        float2 bz = *(const float2*)(bfc + n_col);
        #pragma unroll
        for (int i = 0; i < 2; i++) {
            int mr0 = m0 + (mf0 + i) * 16 + g;
            if (mr0 < B) {
                float2 v0 = make_float2(acc[i][j][0] + bz.x, acc[i][j][1] + bz.y);
                *(float2*)(out + (size_t)mr0 * NOUT + n_col) = v0;
            }
            int mr1 = mr0 + 8;
            if (mr1 < B) {
                float2 v1 = make_float2(acc[i][j][2] + bz.x, acc[i][j][3] + bz.y);
                *(float2*)(out + (size_t)mr1 * NOUT + n_col) = v1;
            }
        }
    }
}

// ===========================================================================
// Launch
// ===========================================================================
extern "C" void kernel_launch(void* const* d_in, const int* in_sizes, int n_in,
                              void* d_out, int out_size) {
    const float* feature = (const float*)d_in[0];
    const int*   ei      = (const int*)  d_in[1];
    const float* ew      = (const float*)d_in[2];
    const float* W1      = (const float*)d_in[3];
    const float* b1      = (const float*)d_in[4];
    const float* W2      = (const float*)d_in[5];
    const float* b2      = (const float*)d_in[6];
    const float* Wfc     = (const float*)d_in[7];
    const float* bfc     = (const float*)d_in[8];
    float*       out     = (float*)d_out;

    const int B = in_sizes[0] / (NNODE * 3);
    const int E = in_sizes[1] / 2;

    build_graph_kernel<<<1, 256>>>(ei, ew, E);
    convert_w_kernel<<<(NOUT * KP + 255) / 256, 256>>>(Wfc);

    const int grid1 = 2048;
    const int bpb = (B + grid1 - 1) / grid1;
    stage1_kernel<<<grid1, 128>>>(feature, W1, b1, W2, b2, B, bpb);

    cudaFuncSetAttribute(fc_mma_kernel,
                         cudaFuncAttributeMaxDynamicSharedMemorySize, FC_SMEM);
    dim3 grid(NOUT / 128, (B + 127) / 128);
    fc_mma_kernel<<<grid, 256, FC_SMEM>>>(bfc, out, B);
}

// round 12
// speedup vs baseline: 2.2651x; 1.5176x over previous
#include <cuda_runtime.h>
#include <cuda_bf16.h>
#include <math.h>

#define NNODE 94
#define MAXB  16384
#define NOUT  6400
#define KP    96          // K padded
#define NS    (KP / 16)   // 6 k-steps

typedef unsigned long long u64;
typedef unsigned int u32;
typedef unsigned short u16;

#define A_RECS (8 * NS * 2 * 32)   // 3072 records per 128-row m tile
#define B_RECS (16 * NS * 32)      // 3072 records per 128-col n tile
#define NMT    (MAXB / 128)        // 128 m tiles
#define NNT    (NOUT / 128)        // 50 n tiles

// Scratch (device globals — no allocation allowed)
__device__ float          g_A  [NNODE * NNODE];     // dense normalized adjacency
__device__ __nv_bfloat16  g_Ahi[MAXB * KP];         // H hi, [m][KP]
__device__ __nv_bfloat16  g_Alo[MAXB * KP];         // H lo
__device__ uint4          g_Arec[NMT * A_RECS];     // packed A fragments
__device__ uint4          g_Brec[NNT * B_RECS];     // packed B fragments

// ===========================================================================
// Helpers
// ===========================================================================
__device__ __forceinline__ u32 smem_u32(const void* p) {
    u32 a;
    asm("{ .reg .u64 t; cvta.to.shared.u64 t, %1; cvt.u32.u64 %0, t; }"
        : "=r"(a) : "l"(p));
    return a;
}
__device__ __forceinline__ void cp16(u32 dst, const void* src) {
    asm volatile("cp.async.cg.shared.global [%0], [%1], 16;"
                 :: "r"(dst), "l"(src) : "memory");
}
__device__ __forceinline__ u16 bf16bits(float f) {
    __nv_bfloat16 h = __float2bfloat16_rn(f);
    return *(u16*)&h;
}

__device__ __forceinline__ void mma_bf16(float& d0, float& d1, float& d2, float& d3,
                                         u32 a0, u32 a1, u32 a2, u32 a3,
                                         u32 b0, u32 b1) {
    asm volatile(
        "mma.sync.aligned.m16n8k16.row.col.f32.bf16.bf16.f32 "
        "{%0,%1,%2,%3}, {%4,%5,%6,%7}, {%8,%9}, {%0,%1,%2,%3};"
        : "+f"(d0), "+f"(d1), "+f"(d2), "+f"(d3)
        : "r"(a0), "r"(a1), "r"(a2), "r"(a3), "r"(b0), "r"(b1));
}

// ===========================================================================
// Kernel 1: build dense normalized adjacency (single block)
// ===========================================================================
__global__ void build_graph_kernel(const int* __restrict__ ei,
                                   const float* __restrict__ ew, int E) {
    __shared__ float deg[NNODE];
    __shared__ float dinv[NNODE];
    int t = threadIdx.x;
    for (int i = t; i < NNODE; i += blockDim.x) deg[i] = 1.0f;
    __syncthreads();
    for (int e = t; e < E; e += blockDim.x)
        atomicAdd(&deg[ei[E + e]], ew[e]);
    __syncthreads();
    for (int i = t; i < NNODE; i += blockDim.x)
        dinv[i] = (deg[i] > 0.0f) ? rsqrtf(deg[i]) : 0.0f;
    for (int i = t; i < NNODE * NNODE; i += blockDim.x) g_A[i] = 0.0f;
    __syncthreads();
    for (int e = t; e < E; e += blockDim.x) {
        int s = ei[e];
        int d = ei[E + e];
        atomicAdd(&g_A[d * NNODE + s], dinv[s] * ew[e] * dinv[d]);
    }
    for (int i = t; i < NNODE; i += blockDim.x)
        atomicAdd(&g_A[i * NNODE + i], dinv[i] * dinv[i]);
}

// ===========================================================================
// Kernel 2: GCN stage, emits hi/lo bf16 [m][96]
// ===========================================================================
__global__ void stage1_kernel(const float* __restrict__ feat,
                              const float* __restrict__ W1,
                              const float* __restrict__ b1,
                              const float* __restrict__ W2,
                              const float* __restrict__ b2,
                              int B, int bpb) {
    __shared__ float As[NNODE * NNODE];
    __shared__ float xw[6][NNODE];
    __shared__ float h1v[NNODE];
    __shared__ float fbuf[NNODE * 3];
    __shared__ float w1s[18], b1s[6], w2s[6], b2s;

    int t = threadIdx.x;
    for (int i = t; i < NNODE * NNODE; i += blockDim.x) As[i] = g_A[i];
    if (t < 18) w1s[t] = W1[t];
    if (t < 6)  { b1s[t] = b1[t]; w2s[t] = W2[t]; }
    if (t == 0) b2s = b2[0];
    __syncthreads();

    for (int bb = 0; bb < bpb; bb++) {
        int b = blockIdx.x * bpb + bb;
        if (b >= B) return;

        for (int i = t; i < NNODE * 3; i += blockDim.x)
            fbuf[i] = feat[b * (NNODE * 3) + i];
        __syncthreads();

        if (t < NNODE) {
            float x0 = fbuf[t * 3 + 0], x1 = fbuf[t * 3 + 1], x2 = fbuf[t * 3 + 2];
            #pragma unroll
            for (int c = 0; c < 6; c++)
                xw[c][t] = x0 * w1s[c] + x1 * w1s[6 + c] + x2 * w1s[12 + c];
        }
        __syncthreads();

        float hz = 0.0f;
        if (t < NNODE) {
            float acc[6] = {0, 0, 0, 0, 0, 0};
            for (int j = 0; j < NNODE; j++) {
                float a = As[t * NNODE + j];
                #pragma unroll
                for (int c = 0; c < 6; c++) acc[c] += a * xw[c][j];
            }
            #pragma unroll
            for (int c = 0; c < 6; c++)
                hz += tanhf(acc[c] + b1s[c]) * w2s[c];
        }
        __syncthreads();
        if (t < NNODE) h1v[t] = hz;
        __syncthreads();

        if (t < KP) {
            float v = 0.0f;
            if (t < NNODE) {
                float acc = 0.0f;
                for (int j = 0; j < NNODE; j++) acc += As[t * NNODE + j] * h1v[j];
                v = tanhf(acc + b2s);
            }
            __nv_bfloat16 h = __float2bfloat16_rn(v);
            g_Ahi[b * KP + t] = h;
            g_Alo[b * KP + t] = __float2bfloat16_rn(v - __bfloat162float(h));
        }
        __syncthreads();
    }
}

// ===========================================================================
// Kernel 3a: repack A into fragment records.
// Record r (per mtile): r = ((mf*NS + s)*2 + rc)*32 + lane
//   m = mtile*128 + mf*16 + rc*8 + (lane>>2), k0 = s*16 + 2*(lane&3)
//   v = {hi[k0,k0+1], hi[k0+8,k0+9], lo[k0,k0+1], lo[k0+8,k0+9]}
// grid (A_RECS/256, NMT)
// ===========================================================================
__global__ void repack_a_kernel(int B) {
    int rr = blockIdx.x * 256 + threadIdx.x;   // 0..3071
    int mtile = blockIdx.y;
    int lane = rr & 31;
    int rc   = (rr >> 5) & 1;
    int rest = rr >> 6;          // 0..47
    int s    = rest % NS;
    int mf   = rest / NS;
    int m  = mtile * 128 + mf * 16 + rc * 8 + (lane >> 2);
    int k0 = s * 16 + 2 * (lane & 3);
    uint4 v = make_uint4(0, 0, 0, 0);
    if (m < B) {
        const u16* ph = (const u16*)g_Ahi + m * KP + k0;
        const u16* pl = (const u16*)g_Alo + m * KP + k0;
        v.x = *(const u32*)ph;
        v.y = *(const u32*)(ph + 8);
        v.z = *(const u32*)pl;
        v.w = *(const u32*)(pl + 8);
    }
    g_Arec[mtile * A_RECS + rr] = v;
}

// ===========================================================================
// Kernel 3b: repack Wfc -> B fragment records (fused hi/lo conversion).
// Record r (per ntile): r = (nf*NS + s)*32 + lane
//   n = ntile*128 + nf*8 + (lane>>2), k0 = s*16 + 2*(lane&3)
// grid (B_RECS/256, NNT)
// ===========================================================================
__global__ void repack_b_kernel(const float* __restrict__ Wfc) {
    int rr = blockIdx.x * 256 + threadIdx.x;   // 0..3071
    int ntile = blockIdx.y;
    int lane = rr & 31;
    int rest = rr >> 5;          // 0..95
    int s    = rest % NS;
    int nf   = rest / NS;
    int n  = ntile * 128 + nf * 8 + (lane >> 2);
    int k0 = s * 16 + 2 * (lane & 3);
    const float* src = Wfc + (size_t)n * NNODE;
    float f[4];
    #pragma unroll
    for (int j = 0; j < 4; j++) {
        int k = k0 + (j >> 1) * 8 + (j & 1);
        f[j] = (k < NNODE) ? src[k] : 0.0f;
    }
    uint4 v;
    u16 h0 = bf16bits(f[0]), h1 = bf16bits(f[1]);
    u16 h2 = bf16bits(f[2]), h3 = bf16bits(f[3]);
    v.x = (u32)h0 | ((u32)h1 << 16);
    v.y = (u32)h2 | ((u32)h3 << 16);
    float l0 = f[0] - __bfloat162float(*(__nv_bfloat16*)&h0);
    float l1 = f[1] - __bfloat162float(*(__nv_bfloat16*)&h1);
    float l2 = f[2] - __bfloat162float(*(__nv_bfloat16*)&h2);
    float l3 = f[3] - __bfloat162float(*(__nv_bfloat16*)&h3);
    v.z = (u32)bf16bits(l0) | ((u32)bf16bits(l1) << 16);
    v.w = (u32)bf16bits(l2) | ((u32)bf16bits(l3) << 16);
    g_Brec[ntile * B_RECS + rr] = v;
}

// ===========================================================================
// Kernel 4: FC GEMM via mma.sync bf16, hi/lo 3-product split.
// Staging is now pure cp.async of pre-packed records.
// ===========================================================================
#define FC_SMEM ((A_RECS + B_RECS) * 16)  // 98304 bytes

__global__ void __launch_bounds__(256, 2)
fc_mma_kernel(const float* __restrict__ bfc, float* __restrict__ out, int B) {
    extern __shared__ char sm[];
    uint4* Af = (uint4*)sm;
    uint4* Bf = (uint4*)sm + A_RECS;

    const int tid  = threadIdx.x;
    const int wid  = tid >> 5;
    const int lane = tid & 31;
    const int m0   = blockIdx.y * 128;
    const int n0   = blockIdx.x * 128;

    // ---- Stage fragments: coalesced 16B async copies ----
    {
        const u32 af = smem_u32(Af);
        const u32 bf = smem_u32(Bf);
        const uint4* Asrc = g_Arec + (size_t)blockIdx.y * A_RECS;
        const uint4* Bsrc = g_Brec + (size_t)blockIdx.x * B_RECS;
        #pragma unroll
        for (int r = 0; r < A_RECS / 256; r++)
            cp16(af + (r * 256 + tid) * 16, Asrc + r * 256 + tid);
        #pragma unroll
        for (int r = 0; r < B_RECS / 256; r++)
            cp16(bf + (r * 256 + tid) * 16, Bsrc + r * 256 + tid);
        asm volatile("cp.async.commit_group;");
        asm volatile("cp.async.wait_group 0;" ::: "memory");
    }
    __syncthreads();

    // Warp tiling: 4 (m) x 2 (n) warps; warp tile = m32 x n64
    const int wm = wid & 3;
    const int wn = wid >> 2;
    const int mf0 = wm * 2;
    const int nf0 = wn * 8;

    float acc[2][8][4];
    #pragma unroll
    for (int i = 0; i < 2; i++)
        #pragma unroll
        for (int j = 0; j < 8; j++)
            #pragma unroll
            for (int c = 0; c < 4; c++) acc[i][j][c] = 0.0f;

    #pragma unroll
    for (int s = 0; s < NS; s++) {
        uint4 ar0[2], ar1[2];
        #pragma unroll
        for (int i = 0; i < 2; i++) {
            int mf = mf0 + i;
            ar0[i] = Af[((mf * NS + s) * 2 + 0) * 32 + lane];
            ar1[i] = Af[((mf * NS + s) * 2 + 1) * 32 + lane];
        }
        #pragma unroll
        for (int j = 0; j < 8; j++) {
            uint4 br = Bf[((nf0 + j) * NS + s) * 32 + lane];
            #pragma unroll
            for (int i = 0; i < 2; i++) {
                mma_bf16(acc[i][j][0], acc[i][j][1], acc[i][j][2], acc[i][j][3],
                         ar0[i].x, ar1[i].x, ar0[i].y, ar1[i].y, br.x, br.y);
                mma_bf16(acc[i][j][0], acc[i][j][1], acc[i][j][2], acc[i][j][3],
                         ar0[i].x, ar1[i].x, ar0[i].y, ar1[i].y, br.z, br.w);
                mma_bf16(acc[i][j][0], acc[i][j][1], acc[i][j][2], acc[i][j][3],
                         ar0[i].z, ar1[i].z, ar0[i].w, ar1[i].w, br.x, br.y);
            }
        }
    }

    // ---- Epilogue ----
    const int g = lane >> 2, t = lane & 3;
    #pragma unroll
    for (int j = 0; j < 8; j++) {
        int n_col = n0 + (nf0 + j) * 8 + 2 * t;
        float2 bz = *(const float2*)(bfc + n_col);
        #pragma unroll
        for (int i = 0; i < 2; i++) {
            int mr0 = m0 + (mf0 + i) * 16 + g;
            if (mr0 < B) {
                float2 v0 = make_float2(acc[i][j][0] + bz.x, acc[i][j][1] + bz.y);
                *(float2*)(out + (size_t)mr0 * NOUT + n_col) = v0;
            }
            int mr1 = mr0 + 8;
            if (mr1 < B) {
                float2 v1 = make_float2(acc[i][j][2] + bz.x, acc[i][j][3] + bz.y);
                *(float2*)(out + (size_t)mr1 * NOUT + n_col) = v1;
            }
        }
    }
}

// ===========================================================================
// Launch
// ===========================================================================
extern "C" void kernel_launch(void* const* d_in, const int* in_sizes, int n_in,
                              void* d_out, int out_size) {
    const float* feature = (const float*)d_in[0];
    const int*   ei      = (const int*)  d_in[1];
    const float* ew      = (const float*)d_in[2];
    const float* W1      = (const float*)d_in[3];
    const float* b1      = (const float*)d_in[4];
    const float* W2      = (const float*)d_in[5];
    const float* b2      = (const float*)d_in[6];
    const float* Wfc     = (const float*)d_in[7];
    const float* bfc     = (const float*)d_in[8];
    float*       out     = (float*)d_out;

    const int B = in_sizes[0] / (NNODE * 3);
    const int E = in_sizes[1] / 2;
    const int nmt = (B + 127) / 128;

    build_graph_kernel<<<1, 256>>>(ei, ew, E);

    {
        dim3 gb(B_RECS / 256, NNT);
        repack_b_kernel<<<gb, 256>>>(Wfc);
    }

    const int grid1 = 2048;
    const int bpb = (B + grid1 - 1) / grid1;
    stage1_kernel<<<grid1, 128>>>(feature, W1, b1, W2, b2, B, bpb);

    {
        dim3 ga(A_RECS / 256, nmt);
        repack_a_kernel<<<ga, 256>>>(B);
    }

    cudaFuncSetAttribute(fc_mma_kernel,
                         cudaFuncAttributeMaxDynamicSharedMemorySize, FC_SMEM);
    dim3 grid(NNT, nmt);
    fc_mma_kernel<<<grid, 256, FC_SMEM>>>(bfc, out, B);
}

// round 13
// speedup vs baseline: 2.8586x; 1.2620x over previous
#include <cuda_runtime.h>
#include <cuda_bf16.h>
#include <math.h>

#define NNODE 94
#define MAXB  16384
#define NOUT  6400
#define KP    96
#define NS    (KP / 16)    // 6

typedef unsigned long long u64;
typedef unsigned int u32;
typedef unsigned short u16;

#define A_RECS  (8 * NS * 2 * 32)    // 3072 (fc A tile, 128 rows)
#define B_RECS  (16 * NS * 32)       // 3072 (fc B tile, 128 cols)
#define AG_RECS (6 * NS * 2 * 32)    // 2304 (adjacency tile, 96 rows)
#define NMT     (MAXB / 128)
#define NNT     (NOUT / 128)
#define NCOLT   (MAXB * 6 / 128)     // 768 col tiles of GEMM1

// Scratch (device globals — no allocation allowed)
__device__ float          g_A   [NNODE * NNODE];
__device__ __nv_bfloat16  g_Ahi [MAXB * KP];
__device__ __nv_bfloat16  g_Alo [MAXB * KP];
__device__ uint4          g_Arec[NMT * A_RECS];
__device__ uint4          g_Brec[NNT * B_RECS];
__device__ uint4          g_AGrec[AG_RECS];          // adjacency fragments (static)
__device__ uint4          g_Zrec[NCOLT * B_RECS];    // GEMM1 B operand records
__device__ uint4          g_Trec[NMT * B_RECS];      // GEMM2 B operand records
__device__ float          g_C1T [(size_t)MAXB * 6 * KP]; // C1 col-major [col][96]

// ===========================================================================
// Helpers
// ===========================================================================
__device__ __forceinline__ u32 smem_u32(const void* p) {
    u32 a;
    asm("{ .reg .u64 t; cvta.to.shared.u64 t, %1; cvt.u32.u64 %0, t; }"
        : "=r"(a) : "l"(p));
    return a;
}
__device__ __forceinline__ void cp16(u32 dst, const void* src) {
    asm volatile("cp.async.cg.shared.global [%0], [%1], 16;"
                 :: "r"(dst), "l"(src) : "memory");
}
__device__ __forceinline__ u16 bf16bits(float f) {
    __nv_bfloat16 h = __float2bfloat16_rn(f);
    return *(u16*)&h;
}
// pack 4 floats into a hi/lo fragment record
__device__ __forceinline__ uint4 pack_rec(float f0, float f1, float f2, float f3) {
    u16 h0 = bf16bits(f0), h1 = bf16bits(f1), h2 = bf16bits(f2), h3 = bf16bits(f3);
    uint4 v;
    v.x = (u32)h0 | ((u32)h1 << 16);
    v.y = (u32)h2 | ((u32)h3 << 16);
    float l0 = f0 - __bfloat162float(*(__nv_bfloat16*)&h0);
    float l1 = f1 - __bfloat162float(*(__nv_bfloat16*)&h1);
    float l2 = f2 - __bfloat162float(*(__nv_bfloat16*)&h2);
    float l3 = f3 - __bfloat162float(*(__nv_bfloat16*)&h3);
    v.z = (u32)bf16bits(l0) | ((u32)bf16bits(l1) << 16);
    v.w = (u32)bf16bits(l2) | ((u32)bf16bits(l3) << 16);
    return v;
}

__device__ __forceinline__ void mma_bf16(float& d0, float& d1, float& d2, float& d3,
                                         u32 a0, u32 a1, u32 a2, u32 a3,
                                         u32 b0, u32 b1) {
    asm volatile(
        "mma.sync.aligned.m16n8k16.row.col.f32.bf16.bf16.f32 "
        "{%0,%1,%2,%3}, {%4,%5,%6,%7}, {%8,%9}, {%0,%1,%2,%3};"
        : "+f"(d0), "+f"(d1), "+f"(d2), "+f"(d3)
        : "r"(a0), "r"(a1), "r"(a2), "r"(a3), "r"(b0), "r"(b1));
}

// ===========================================================================
// Kernel: build dense normalized adjacency (single block)
// ===========================================================================
__global__ void build_graph_kernel(const int* __restrict__ ei,
                                   const float* __restrict__ ew, int E) {
    __shared__ float deg[NNODE];
    __shared__ float dinv[NNODE];
    int t = threadIdx.x;
    for (int i = t; i < NNODE; i += blockDim.x) deg[i] = 1.0f;
    __syncthreads();
    for (int e = t; e < E; e += blockDim.x)
        atomicAdd(&deg[ei[E + e]], ew[e]);
    __syncthreads();
    for (int i = t; i < NNODE; i += blockDim.x)
        dinv[i] = (deg[i] > 0.0f) ? rsqrtf(deg[i]) : 0.0f;
    for (int i = t; i < NNODE * NNODE; i += blockDim.x) g_A[i] = 0.0f;
    __syncthreads();
    for (int e = t; e < E; e += blockDim.x) {
        int s = ei[e];
        int d = ei[E + e];
        atomicAdd(&g_A[d * NNODE + s], dinv[s] * ew[e] * dinv[d]);
    }
    for (int i = t; i < NNODE; i += blockDim.x)
        atomicAdd(&g_A[i * NNODE + i], dinv[i] * dinv[i]);
}

// ===========================================================================
// Kernel: pack adjacency into 96x96 A-fragment records (hi/lo)
// r = ((mf*NS + s)*2 + rc)*32 + lane ; m = mf*16+rc*8+g ; k0 = s*16+2t
// ===========================================================================
__global__ void repack_ag_kernel() {
    int r = blockIdx.x * 256 + threadIdx.x;
    if (r >= AG_RECS) return;
    int lane = r & 31;
    int rc   = (r >> 5) & 1;
    int rest = r >> 6;
    int s    = rest % NS;
    int mf   = rest / NS;
    int m  = mf * 16 + rc * 8 + (lane >> 2);
    int k0 = s * 16 + 2 * (lane & 3);
    float f[4];
    #pragma unroll
    for (int j = 0; j < 4; j++) {
        int k = k0 + (j >> 1) * 8 + (j & 1);
        f[j] = (m < NNODE && k < NNODE) ? g_A[m * NNODE + k] : 0.0f;
    }
    g_AGrec[r] = pack_rec(f[0], f[1], f[2], f[3]);
}

// ===========================================================================
// Kernel: Z records.  Z[j][col] = sum_d X[b][j][d] W1[d][c], col = b*6+c
// One block per 128-col tile. xws in dynamic smem: [bl][94][6]
// ===========================================================================
#define XZ_SMEM (23 * NNODE * 6 * 4)   // 51888 bytes

__global__ void __launch_bounds__(256)
xz_kernel(const float* __restrict__ feat, const float* __restrict__ W1, int B) {
    extern __shared__ float xws[];
    __shared__ float w1s[18];
    const int tid = threadIdx.x;
    const int col0 = blockIdx.x * 128;
    const int bstart = col0 / 6;
    const int nb = (col0 + 127) / 6 - bstart + 1;  // <= 23

    if (tid < 18) w1s[tid] = W1[tid];
    __syncthreads();

    for (int idx = tid; idx < nb * NNODE; idx += 256) {
        int bl = idx / NNODE, j = idx - bl * NNODE;
        int b = bstart + bl;
        float x0 = 0, x1 = 0, x2 = 0;
        if (b < B) {
            const float* p = feat + (size_t)b * (NNODE * 3) + j * 3;
            x0 = p[0]; x1 = p[1]; x2 = p[2];
        }
        float* o = xws + (bl * NNODE + j) * 6;
        #pragma unroll
        for (int c = 0; c < 6; c++)
            o[c] = x0 * w1s[c] + x1 * w1s[6 + c] + x2 * w1s[12 + c];
    }
    __syncthreads();

    for (int r = tid; r < B_RECS; r += 256) {
        int lane = r & 31;
        int s    = (r >> 5) % NS;
        int nf   = r / (NS * 32);
        int col = col0 + nf * 8 + (lane >> 2);
        int b = col / 6, c = col - b * 6;
        int bl = b - bstart;
        int k0 = s * 16 + 2 * (lane & 3);
        float f[4];
        #pragma unroll
        for (int jj = 0; jj < 4; jj++) {
            int j = k0 + (jj >> 1) * 8 + (jj & 1);
            f[jj] = (j < NNODE && b < B) ? xws[(bl * NNODE + j) * 6 + c] : 0.0f;
        }
        g_Zrec[(size_t)blockIdx.x * B_RECS + r] = pack_rec(f[0], f[1], f[2], f[3]);
    }
}

// ===========================================================================
// GEMM1: C1[n][col] = sum_j A[n][j] Z[j][col].  M=96, Ntile=128, K=96.
// Writes C1 col-major: g_C1T[col*96 + n]
// ===========================================================================
#define G_SMEM ((AG_RECS + B_RECS) * 16)   // 86016

__global__ void __launch_bounds__(256, 2)
gemm1_kernel() {
    extern __shared__ char sm[];
    uint4* Af = (uint4*)sm;
    uint4* Bf = (uint4*)sm + AG_RECS;
    const int tid = threadIdx.x;
    const int wid = tid >> 5, lane = tid & 31;
    const int col0 = blockIdx.x * 128;

    {
        const u32 af = smem_u32(Af), bf = smem_u32(Bf);
        const uint4* Bsrc = g_Zrec + (size_t)blockIdx.x * B_RECS;
        #pragma unroll
        for (int r = 0; r < AG_RECS / 256; r++)
            cp16(af + (r * 256 + tid) * 16, g_AGrec + r * 256 + tid);
        #pragma unroll
        for (int r = 0; r < B_RECS / 256; r++)
            cp16(bf + (r * 256 + tid) * 16, Bsrc + r * 256 + tid);
        asm volatile("cp.async.commit_group;");
        asm volatile("cp.async.wait_group 0;" ::: "memory");
    }
    __syncthreads();

    const int mf0 = (wid & 1) * 3;
    const int nf0 = (wid >> 1) * 4;

    float acc[3][4][4];
    #pragma unroll
    for (int i = 0; i < 3; i++)
        #pragma unroll
        for (int j = 0; j < 4; j++)
            #pragma unroll
            for (int c = 0; c < 4; c++) acc[i][j][c] = 0.0f;

    #pragma unroll
    for (int s = 0; s < NS; s++) {
        uint4 ar0[3], ar1[3];
        #pragma unroll
        for (int i = 0; i < 3; i++) {
            int mf = mf0 + i;
            ar0[i] = Af[((mf * NS + s) * 2 + 0) * 32 + lane];
            ar1[i] = Af[((mf * NS + s) * 2 + 1) * 32 + lane];
        }
        #pragma unroll
        for (int j = 0; j < 4; j++) {
            uint4 br = Bf[((nf0 + j) * NS + s) * 32 + lane];
            #pragma unroll
            for (int i = 0; i < 3; i++) {
                mma_bf16(acc[i][j][0], acc[i][j][1], acc[i][j][2], acc[i][j][3],
                         ar0[i].x, ar1[i].x, ar0[i].y, ar1[i].y, br.x, br.y);
                mma_bf16(acc[i][j][0], acc[i][j][1], acc[i][j][2], acc[i][j][3],
                         ar0[i].x, ar1[i].x, ar0[i].y, ar1[i].y, br.z, br.w);
                mma_bf16(acc[i][j][0], acc[i][j][1], acc[i][j][2], acc[i][j][3],
                         ar0[i].z, ar1[i].z, ar0[i].w, ar1[i].w, br.x, br.y);
            }
        }
    }

    const int g = lane >> 2, t = lane & 3;
    #pragma unroll
    for (int j = 0; j < 4; j++) {
        size_t col = col0 + (nf0 + j) * 8 + 2 * t;
        #pragma unroll
        for (int i = 0; i < 3; i++) {
            int row = (mf0 + i) * 16 + g;
            g_C1T[col * KP + row]           = acc[i][j][0];
            g_C1T[(col + 1) * KP + row]     = acc[i][j][1];
            g_C1T[col * KP + row + 8]       = acc[i][j][2];
            g_C1T[(col + 1) * KP + row + 8] = acc[i][j][3];
        }
    }
}

// ===========================================================================
// mid: T[j][b] = sum_c tanh(C1[j][b*6+c] + b1[c]) * W2[c] -> Trec records
// One block per 32 b's.
// ===========================================================================
#define MID_SMEM ((192 * KP + 32 * 97) * 4)   // 86144

__global__ void __launch_bounds__(256)
mid_kernel(const float* __restrict__ b1, const float* __restrict__ W2, int B) {
    extern __shared__ float smf[];
    float* Cs = smf;                 // [192][96]
    float* Ts = smf + 192 * KP;      // [32][97]
    __shared__ float b1s[6], w2s[6];
    const int tid = threadIdx.x;
    const int b0 = blockIdx.x * 32;

    if (tid < 6) { b1s[tid] = b1[tid]; w2s[tid] = W2[tid]; }
    {
        const u32 cs = smem_u32(Cs);
        const uint4* src = (const uint4*)(g_C1T + (size_t)b0 * 6 * KP);
        #pragma unroll
        for (int r = 0; r < 18; r++)
            cp16(cs + (r * 256 + tid) * 16, src + r * 256 + tid);
        asm volatile("cp.async.commit_group;");
        asm volatile("cp.async.wait_group 0;" ::: "memory");
    }
    __syncthreads();

    for (int idx = tid; idx < 32 * KP; idx += 256) {
        int bl = idx / KP, j = idx - bl * KP;
        float tv = 0.0f;
        #pragma unroll
        for (int c = 0; c < 6; c++)
            tv += tanhf(Cs[(bl * 6 + c) * KP + j] + b1s[c]) * w2s[c];
        Ts[bl * 97 + j] = tv;
    }
    __syncthreads();

    const int tile = blockIdx.x >> 2;
    const int sub  = blockIdx.x & 3;
    for (int r = tid; r < 768; r += 256) {
        int lane = r & 31;
        int s    = (r >> 5) % NS;
        int nfl  = r / (NS * 32);          // 0..3
        int nf   = sub * 4 + nfl;
        int bl   = nfl * 8 + (lane >> 2);
        int k0   = s * 16 + 2 * (lane & 3);
        float f0 = Ts[bl * 97 + k0];
        float f1 = Ts[bl * 97 + k0 + 1];
        float f2 = Ts[bl * 97 + k0 + 8];
        float f3 = Ts[bl * 97 + k0 + 9];
        g_Trec[(size_t)tile * B_RECS + (nf * NS + s) * 32 + lane] =
            pack_rec(f0, f1, f2, f3);
    }
}

// ===========================================================================
// GEMM2: H[n][b] = tanh(sum_j A[n][j] T[j][b] + b2) -> g_Ahi/g_Alo[b][n]
// ===========================================================================
__global__ void __launch_bounds__(256, 2)
gemm2_kernel(const float* __restrict__ b2, int B) {
    extern __shared__ char sm[];
    uint4* Af = (uint4*)sm;
    uint4* Bf = (uint4*)sm + AG_RECS;
    const int tid = threadIdx.x;
    const int wid = tid >> 5, lane = tid & 31;
    const int b0 = blockIdx.x * 128;

    {
        const u32 af = smem_u32(Af), bf = smem_u32(Bf);
        const uint4* Bsrc = g_Trec + (size_t)blockIdx.x * B_RECS;
        #pragma unroll
        for (int r = 0; r < AG_RECS / 256; r++)
            cp16(af + (r * 256 + tid) * 16, g_AGrec + r * 256 + tid);
        #pragma unroll
        for (int r = 0; r < B_RECS / 256; r++)
            cp16(bf + (r * 256 + tid) * 16, Bsrc + r * 256 + tid);
        asm volatile("cp.async.commit_group;");
        asm volatile("cp.async.wait_group 0;" ::: "memory");
    }
    __syncthreads();

    const int mf0 = (wid & 1) * 3;
    const int nf0 = (wid >> 1) * 4;

    float acc[3][4][4];
    #pragma unroll
    for (int i = 0; i < 3; i++)
        #pragma unroll
        for (int j = 0; j < 4; j++)
            #pragma unroll
            for (int c = 0; c < 4; c++) acc[i][j][c] = 0.0f;

    #pragma unroll
    for (int s = 0; s < NS; s++) {
        uint4 ar0[3], ar1[3];
        #pragma unroll
        for (int i = 0; i < 3; i++) {
            int mf = mf0 + i;
            ar0[i] = Af[((mf * NS + s) * 2 + 0) * 32 + lane];
            ar1[i] = Af[((mf * NS + s) * 2 + 1) * 32 + lane];
        }
        #pragma unroll
        for (int j = 0; j < 4; j++) {
            uint4 br = Bf[((nf0 + j) * NS + s) * 32 + lane];
            #pragma unroll
            for (int i = 0; i < 3; i++) {
                mma_bf16(acc[i][j][0], acc[i][j][1], acc[i][j][2], acc[i][j][3],
                         ar0[i].x, ar1[i].x, ar0[i].y, ar1[i].y, br.x, br.y);
                mma_bf16(acc[i][j][0], acc[i][j][1], acc[i][j][2], acc[i][j][3],
                         ar0[i].x, ar1[i].x, ar0[i].y, ar1[i].y, br.z, br.w);
                mma_bf16(acc[i][j][0], acc[i][j][1], acc[i][j][2], acc[i][j][3],
                         ar0[i].z, ar1[i].z, ar0[i].w, ar1[i].w, br.x, br.y);
            }
        }
    }

    const float b2v = b2[0];
    const int g = lane >> 2, t = lane & 3;
    #pragma unroll
    for (int j = 0; j < 4; j++) {
        int b = b0 + (nf0 + j) * 8 + 2 * t;
        #pragma unroll
        for (int i = 0; i < 3; i++) {
            int n = (mf0 + i) * 16 + g;
            #pragma unroll
            for (int q = 0; q < 4; q++) {
                int bb = b + (q & 1);
                int nn = n + (q >> 1) * 8;
                if (bb < B) {
                    float h = tanhf(acc[i][j][q] + b2v);
                    __nv_bfloat16 hh = __float2bfloat16_rn(h);
                    g_Ahi[bb * KP + nn] = hh;
                    g_Alo[bb * KP + nn] =
                        __float2bfloat16_rn(h - __bfloat162float(hh));
                }
            }
        }
    }
}

// ===========================================================================
// repack A (fc operand) from g_Ahi/g_Alo — unchanged
// ===========================================================================
__global__ void repack_a_kernel(int B) {
    int rr = blockIdx.x * 256 + threadIdx.x;
    int mtile = blockIdx.y;
    int lane = rr & 31;
    int rc   = (rr >> 5) & 1;
    int rest = rr >> 6;
    int s    = rest % NS;
    int mf   = rest / NS;
    int m  = mtile * 128 + mf * 16 + rc * 8 + (lane >> 2);
    int k0 = s * 16 + 2 * (lane & 3);
    uint4 v = make_uint4(0, 0, 0, 0);
    if (m < B) {
        const u16* ph = (const u16*)g_Ahi + m * KP + k0;
        const u16* pl = (const u16*)g_Alo + m * KP + k0;
        v.x = *(const u32*)ph;
        v.y = *(const u32*)(ph + 8);
        v.z = *(const u32*)pl;
        v.w = *(const u32*)(pl + 8);
    }
    g_Arec[mtile * A_RECS + rr] = v;
}

// ===========================================================================
// repack Wfc -> B fragment records — unchanged
// ===========================================================================
__global__ void repack_b_kernel(const float* __restrict__ Wfc) {
    int rr = blockIdx.x * 256 + threadIdx.x;
    int ntile = blockIdx.y;
    int lane = rr & 31;
    int rest = rr >> 5;
    int s    = rest % NS;
    int nf   = rest / NS;
    int n  = ntile * 128 + nf * 8 + (lane >> 2);
    int k0 = s * 16 + 2 * (lane & 3);
    const float* src = Wfc + (size_t)n * NNODE;
    float f[4];
    #pragma unroll
    for (int j = 0; j < 4; j++) {
        int k = k0 + (j >> 1) * 8 + (j & 1);
        f[j] = (k < NNODE) ? src[k] : 0.0f;
    }
    g_Brec[ntile * B_RECS + rr] = pack_rec(f[0], f[1], f[2], f[3]);
}

// ===========================================================================
// FC GEMM — unchanged from R12
// ===========================================================================
#define FC_SMEM ((A_RECS + B_RECS) * 16)  // 98304

__global__ void __launch_bounds__(256, 2)
fc_mma_kernel(const float* __restrict__ bfc, float* __restrict__ out, int B) {
    extern __shared__ char sm[];
    uint4* Af = (uint4*)sm;
    uint4* Bf = (uint4*)sm + A_RECS;

    const int tid  = threadIdx.x;
    const int wid  = tid >> 5;
    const int lane = tid & 31;
    const int m0   = blockIdx.y * 128;
    const int n0   = blockIdx.x * 128;

    {
        const u32 af = smem_u32(Af);
        const u32 bf = smem_u32(Bf);
        const uint4* Asrc = g_Arec + (size_t)blockIdx.y * A_RECS;
        const uint4* Bsrc = g_Brec + (size_t)blockIdx.x * B_RECS;
        #pragma unroll
        for (int r = 0; r < A_RECS / 256; r++)
            cp16(af + (r * 256 + tid) * 16, Asrc + r * 256 + tid);
        #pragma unroll
        for (int r = 0; r < B_RECS / 256; r++)
            cp16(bf + (r * 256 + tid) * 16, Bsrc + r * 256 + tid);
        asm volatile("cp.async.commit_group;");
        asm volatile("cp.async.wait_group 0;" ::: "memory");
    }
    __syncthreads();

    const int wm = wid & 3;
    const int wn = wid >> 2;
    const int mf0 = wm * 2;
    const int nf0 = wn * 8;

    float acc[2][8][4];
    #pragma unroll
    for (int i = 0; i < 2; i++)
        #pragma unroll
        for (int j = 0; j < 8; j++)
            #pragma unroll
            for (int c = 0; c < 4; c++) acc[i][j][c] = 0.0f;

    #pragma unroll
    for (int s = 0; s < NS; s++) {
        uint4 ar0[2], ar1[2];
        #pragma unroll
        for (int i = 0; i < 2; i++) {
            int mf = mf0 + i;
            ar0[i] = Af[((mf * NS + s) * 2 + 0) * 32 + lane];
            ar1[i] = Af[((mf * NS + s) * 2 + 1) * 32 + lane];
        }
        #pragma unroll
        for (int j = 0; j < 8; j++) {
            uint4 br = Bf[((nf0 + j) * NS + s) * 32 + lane];
            #pragma unroll
            for (int i = 0; i < 2; i++) {
                mma_bf16(acc[i][j][0], acc[i][j][1], acc[i][j][2], acc[i][j][3],
                         ar0[i].x, ar1[i].x, ar0[i].y, ar1[i].y, br.x, br.y);
                mma_bf16(acc[i][j][0], acc[i][j][1], acc[i][j][2], acc[i][j][3],
                         ar0[i].x, ar1[i].x, ar0[i].y, ar1[i].y, br.z, br.w);
                mma_bf16(acc[i][j][0], acc[i][j][1], acc[i][j][2], acc[i][j][3],
                         ar0[i].z, ar1[i].z, ar0[i].w, ar1[i].w, br.x, br.y);
            }
        }
    }

    const int g = lane >> 2, t = lane & 3;
    #pragma unroll
    for (int j = 0; j < 8; j++) {
        int n_col = n0 + (nf0 + j) * 8 + 2 * t;
        float2 bz = *(const float2*)(bfc + n_col);
        #pragma unroll
        for (int i = 0; i < 2; i++) {
            int mr0 = m0 + (mf0 + i) * 16 + g;
            if (mr0 < B) {
                float2 v0 = make_float2(acc[i][j][0] + bz.x, acc[i][j][1] + bz.y);
                *(float2*)(out + (size_t)mr0 * NOUT + n_col) = v0;
            }
            int mr1 = mr0 + 8;
            if (mr1 < B) {
                float2 v1 = make_float2(acc[i][j][2] + bz.x, acc[i][j][3] + bz.y);
                *(float2*)(out + (size_t)mr1 * NOUT + n_col) = v1;
            }
        }
    }
}

// ===========================================================================
// Launch
// ===========================================================================
extern "C" void kernel_launch(void* const* d_in, const int* in_sizes, int n_in,
                              void* d_out, int out_size) {
    const float* feature = (const float*)d_in[0];
    const int*   ei      = (const int*)  d_in[1];
    const float* ew      = (const float*)d_in[2];
    const float* W1      = (const float*)d_in[3];
    const float* b1      = (const float*)d_in[4];
    const float* W2      = (const float*)d_in[5];
    const float* b2      = (const float*)d_in[6];
    const float* Wfc     = (const float*)d_in[7];
    const float* bfc     = (const float*)d_in[8];
    float*       out     = (float*)d_out;

    const int B = in_sizes[0] / (NNODE * 3);
    const int E = in_sizes[1] / 2;
    const int nmt   = (B + 127) / 128;
    const int ncolt = (B * 6 + 127) / 128;
    const int nmid  = (B + 31) / 32;

    cudaFuncSetAttribute(xz_kernel,   cudaFuncAttributeMaxDynamicSharedMemorySize, XZ_SMEM);
    cudaFuncSetAttribute(gemm1_kernel,cudaFuncAttributeMaxDynamicSharedMemorySize, G_SMEM);
    cudaFuncSetAttribute(mid_kernel,  cudaFuncAttributeMaxDynamicSharedMemorySize, MID_SMEM);
    cudaFuncSetAttribute(gemm2_kernel,cudaFuncAttributeMaxDynamicSharedMemorySize, G_SMEM);
    cudaFuncSetAttribute(fc_mma_kernel,cudaFuncAttributeMaxDynamicSharedMemorySize, FC_SMEM);

    build_graph_kernel<<<1, 256>>>(ei, ew, E);
    repack_ag_kernel<<<(AG_RECS + 255) / 256, 256>>>();

    { dim3 gb(B_RECS / 256, NNT); repack_b_kernel<<<gb, 256>>>(Wfc); }

    xz_kernel<<<ncolt, 256, XZ_SMEM>>>(feature, W1, B);
    gemm1_kernel<<<ncolt, 256, G_SMEM>>>();
    mid_kernel<<<nmid, 256, MID_SMEM>>>(b1, W2, B);
    gemm2_kernel<<<nmt, 256, G_SMEM>>>(b2, B);

    { dim3 ga(A_RECS / 256, nmt); repack_a_kernel<<<ga, 256>>>(B); }

    dim3 grid(NNT, nmt);
    fc_mma_kernel<<<grid, 256, FC_SMEM>>>(bfc, out, B);
}

// round 14
// speedup vs baseline: 2.9098x; 1.0179x over previous
#include <cuda_runtime.h>
#include <cuda_bf16.h>
#include <math.h>

#define NNODE 94
#define MAXB  16384
#define NOUT  6400
#define KP    96
#define NS    (KP / 16)    // 6

typedef unsigned long long u64;
typedef unsigned int u32;
typedef unsigned short u16;

#define A_RECS  (8 * NS * 2 * 32)    // 3072 (fc A tile, 128 rows)
#define B_RECS  (16 * NS * 32)       // 3072 (128-col B tile)
#define AG_RECS (6 * NS * 2 * 32)    // 2304 (adjacency tile, 96 rows)
#define NMT     (MAXB / 128)         // 128
#define NNT     (NOUT / 128)         // 50
#define NT21    ((MAXB + 20) / 21)   // 781 gemm1 tiles (21 b's each)

// Scratch (device globals — no allocation allowed)
__device__ float g_A    [NNODE * NNODE];
__device__ uint4 g_Arec [NMT * A_RECS];
__device__ uint4 g_Brec [NNT * B_RECS];
__device__ uint4 g_AGrec[AG_RECS];
__device__ uint4 g_Zrec [(size_t)NT21 * B_RECS];
__device__ uint4 g_Trec [NMT * B_RECS];
__device__ float g_T    [MAXB * KP];     // T[b][96]

// ===========================================================================
// Helpers
// ===========================================================================
__device__ __forceinline__ u32 smem_u32(const void* p) {
    u32 a;
    asm("{ .reg .u64 t; cvta.to.shared.u64 t, %1; cvt.u32.u64 %0, t; }"
        : "=r"(a) : "l"(p));
    return a;
}
__device__ __forceinline__ void cp16(u32 dst, const void* src) {
    asm volatile("cp.async.cg.shared.global [%0], [%1], 16;"
                 :: "r"(dst), "l"(src) : "memory");
}
__device__ __forceinline__ u16 bf16bits(float f) {
    __nv_bfloat16 h = __float2bfloat16_rn(f);
    return *(u16*)&h;
}
__device__ __forceinline__ uint4 pack_rec(float f0, float f1, float f2, float f3) {
    u16 h0 = bf16bits(f0), h1 = bf16bits(f1), h2 = bf16bits(f2), h3 = bf16bits(f3);
    uint4 v;
    v.x = (u32)h0 | ((u32)h1 << 16);
    v.y = (u32)h2 | ((u32)h3 << 16);
    float l0 = f0 - __bfloat162float(*(__nv_bfloat16*)&h0);
    float l1 = f1 - __bfloat162float(*(__nv_bfloat16*)&h1);
    float l2 = f2 - __bfloat162float(*(__nv_bfloat16*)&h2);
    float l3 = f3 - __bfloat162float(*(__nv_bfloat16*)&h3);
    v.z = (u32)bf16bits(l0) | ((u32)bf16bits(l1) << 16);
    v.w = (u32)bf16bits(l2) | ((u32)bf16bits(l3) << 16);
    return v;
}

__device__ __forceinline__ void mma_bf16(float& d0, float& d1, float& d2, float& d3,
                                         u32 a0, u32 a1, u32 a2, u32 a3,
                                         u32 b0, u32 b1) {
    asm volatile(
        "mma.sync.aligned.m16n8k16.row.col.f32.bf16.bf16.f32 "
        "{%0,%1,%2,%3}, {%4,%5,%6,%7}, {%8,%9}, {%0,%1,%2,%3};"
        : "+f"(d0), "+f"(d1), "+f"(d2), "+f"(d3)
        : "r"(a0), "r"(a1), "r"(a2), "r"(a3), "r"(b0), "r"(b1));
}

// ===========================================================================
// build dense normalized adjacency (single block)
// ===========================================================================
__global__ void build_graph_kernel(const int* __restrict__ ei,
                                   const float* __restrict__ ew, int E) {
    __shared__ float deg[NNODE];
    __shared__ float dinv[NNODE];
    int t = threadIdx.x;
    for (int i = t; i < NNODE; i += blockDim.x) deg[i] = 1.0f;
    __syncthreads();
    for (int e = t; e < E; e += blockDim.x)
        atomicAdd(&deg[ei[E + e]], ew[e]);
    __syncthreads();
    for (int i = t; i < NNODE; i += blockDim.x)
        dinv[i] = (deg[i] > 0.0f) ? rsqrtf(deg[i]) : 0.0f;
    for (int i = t; i < NNODE * NNODE; i += blockDim.x) g_A[i] = 0.0f;
    __syncthreads();
    for (int e = t; e < E; e += blockDim.x) {
        int s = ei[e];
        int d = ei[E + e];
        atomicAdd(&g_A[d * NNODE + s], dinv[s] * ew[e] * dinv[d]);
    }
    for (int i = t; i < NNODE; i += blockDim.x)
        atomicAdd(&g_A[i * NNODE + i], dinv[i] * dinv[i]);
}

// ===========================================================================
// adjacency -> 96x96 A-fragment records
// ===========================================================================
__global__ void repack_ag_kernel() {
    int r = blockIdx.x * 256 + threadIdx.x;
    if (r >= AG_RECS) return;
    int lane = r & 31;
    int rc   = (r >> 5) & 1;
    int rest = r >> 6;
    int s    = rest % NS;
    int mf   = rest / NS;
    int m  = mf * 16 + rc * 8 + (lane >> 2);
    int k0 = s * 16 + 2 * (lane & 3);
    float f[4];
    #pragma unroll
    for (int j = 0; j < 4; j++) {
        int k = k0 + (j >> 1) * 8 + (j & 1);
        f[j] = (m < NNODE && k < NNODE) ? g_A[m * NNODE + k] : 0.0f;
    }
    g_AGrec[r] = pack_rec(f[0], f[1], f[2], f[3]);
}

// ===========================================================================
// Wfc -> B fragment records, WITH column permutation for STG.128 epilogue.
// Logical slot (nf, g) sources physical col 16*(nf>>1)+4*(g>>1)+2*(nf&1)+(g&1)
// ===========================================================================
__global__ void repack_b_kernel(const float* __restrict__ Wfc) {
    int rr = blockIdx.x * 256 + threadIdx.x;
    int ntile = blockIdx.y;
    int lane = rr & 31;
    int rest = rr >> 5;
    int s    = rest % NS;
    int nf   = rest / NS;
    int g    = lane >> 2;
    int n_phys = 16 * (nf >> 1) + 4 * (g >> 1) + 2 * (nf & 1) + (g & 1);
    int n  = ntile * 128 + n_phys;
    int k0 = s * 16 + 2 * (lane & 3);
    const float* src = Wfc + (size_t)n * NNODE;
    float f[4];
    #pragma unroll
    for (int j = 0; j < 4; j++) {
        int k = k0 + (j >> 1) * 8 + (j & 1);
        f[j] = (k < NNODE) ? src[k] : 0.0f;
    }
    g_Brec[ntile * B_RECS + rr] = pack_rec(f[0], f[1], f[2], f[3]);
}

// ===========================================================================
// xz: Z records for 126-col (21-batch) tiles.
// Z[j][col] = sum_d X[b][j][d] W1[d][c], col = local b*6+c; cols 126/127 zero
// ===========================================================================
#define XZ_SMEM (21 * NNODE * 6 * 4)   // 47376 bytes

__global__ void __launch_bounds__(256)
xz_kernel(const float* __restrict__ feat, const float* __restrict__ W1, int B) {
    extern __shared__ float xws[];
    __shared__ float w1s[18];
    const int tid = threadIdx.x;
    const int bstart = blockIdx.x * 21;

    if (tid < 18) w1s[tid] = W1[tid];
    __syncthreads();

    for (int idx = tid; idx < 21 * NNODE; idx += 256) {
        int bl = idx / NNODE, j = idx - bl * NNODE;
        int b = bstart + bl;
        float x0 = 0, x1 = 0, x2 = 0;
        if (b < B) {
            const float* p = feat + (size_t)b * (NNODE * 3) + j * 3;
            x0 = p[0]; x1 = p[1]; x2 = p[2];
        }
        float* o = xws + (bl * NNODE + j) * 6;
        #pragma unroll
        for (int c = 0; c < 6; c++)
            o[c] = x0 * w1s[c] + x1 * w1s[6 + c] + x2 * w1s[12 + c];
    }
    __syncthreads();

    for (int r = tid; r < B_RECS; r += 256) {
        int lane = r & 31;
        int s    = (r >> 5) % NS;
        int nf   = r / (NS * 32);
        int col  = nf * 8 + (lane >> 2);       // logical col 0..127
        int k0   = s * 16 + 2 * (lane & 3);
        uint4 v = make_uint4(0, 0, 0, 0);
        if (col < 126) {
            int bl = col / 6, c = col - (col / 6) * 6;
            if (bstart + bl < B) {
                float f[4];
                #pragma unroll
                for (int jj = 0; jj < 4; jj++) {
                    int j = k0 + (jj >> 1) * 8 + (jj & 1);
                    f[jj] = (j < NNODE) ? xws[(bl * NNODE + j) * 6 + c] : 0.0f;
                }
                v = pack_rec(f[0], f[1], f[2], f[3]);
            }
        }
        g_Zrec[(size_t)blockIdx.x * B_RECS + r] = v;
    }
}

// ===========================================================================
// GEMM1 fused: C1 = A·Z, then T[j][b] = sum_c tanh(C1+b1)·W2 in-block.
// Writes plain g_T[b][96].
// ===========================================================================
#define G_SMEM ((AG_RECS + B_RECS) * 16)   // 86016

__global__ void __launch_bounds__(256, 2)
gemm1_kernel(const float* __restrict__ b1, const float* __restrict__ W2, int B) {
    extern __shared__ char sm[];
    uint4* Af = (uint4*)sm;
    uint4* Bf = (uint4*)sm + AG_RECS;
    float* Cs = (float*)sm;                 // reused after mainloop: [128][97]
    __shared__ float b1s[6], w2s[6];
    const int tid = threadIdx.x;
    const int wid = tid >> 5, lane = tid & 31;
    const int bstart = blockIdx.x * 21;

    if (tid < 6) { b1s[tid] = b1[tid]; w2s[tid] = W2[tid]; }
    {
        const u32 af = smem_u32(Af), bf = smem_u32(Bf);
        const uint4* Bsrc = g_Zrec + (size_t)blockIdx.x * B_RECS;
        #pragma unroll
        for (int r = 0; r < AG_RECS / 256; r++)
            cp16(af + (r * 256 + tid) * 16, g_AGrec + r * 256 + tid);
        #pragma unroll
        for (int r = 0; r < B_RECS / 256; r++)
            cp16(bf + (r * 256 + tid) * 16, Bsrc + r * 256 + tid);
        asm volatile("cp.async.commit_group;");
        asm volatile("cp.async.wait_group 0;" ::: "memory");
    }
    __syncthreads();

    const int mf0 = (wid & 1) * 3;
    const int nf0 = (wid >> 1) * 4;

    float acc[3][4][4];
    #pragma unroll
    for (int i = 0; i < 3; i++)
        #pragma unroll
        for (int j = 0; j < 4; j++)
            #pragma unroll
            for (int c = 0; c < 4; c++) acc[i][j][c] = 0.0f;

    #pragma unroll
    for (int s = 0; s < NS; s++) {
        uint4 ar0[3], ar1[3];
        #pragma unroll
        for (int i = 0; i < 3; i++) {
            int mf = mf0 + i;
            ar0[i] = Af[((mf * NS + s) * 2 + 0) * 32 + lane];
            ar1[i] = Af[((mf * NS + s) * 2 + 1) * 32 + lane];
        }
        #pragma unroll
        for (int j = 0; j < 4; j++) {
            uint4 br = Bf[((nf0 + j) * NS + s) * 32 + lane];
            #pragma unroll
            for (int i = 0; i < 3; i++) {
                mma_bf16(acc[i][j][0], acc[i][j][1], acc[i][j][2], acc[i][j][3],
                         ar0[i].x, ar1[i].x, ar0[i].y, ar1[i].y, br.x, br.y);
                mma_bf16(acc[i][j][0], acc[i][j][1], acc[i][j][2], acc[i][j][3],
                         ar0[i].x, ar1[i].x, ar0[i].y, ar1[i].y, br.z, br.w);
                mma_bf16(acc[i][j][0], acc[i][j][1], acc[i][j][2], acc[i][j][3],
                         ar0[i].z, ar1[i].z, ar0[i].w, ar1[i].w, br.x, br.y);
            }
        }
    }

    __syncthreads();   // staging smem dead -> reuse as Cs

    const int g = lane >> 2, t = lane & 3;
    #pragma unroll
    for (int j = 0; j < 4; j++) {
        int col = (nf0 + j) * 8 + 2 * t;
        #pragma unroll
        for (int i = 0; i < 3; i++) {
            int row = (mf0 + i) * 16 + g;
            Cs[col * 97 + row]             = acc[i][j][0];
            Cs[(col + 1) * 97 + row]       = acc[i][j][1];
            Cs[col * 97 + row + 8]         = acc[i][j][2];
            Cs[(col + 1) * 97 + row + 8]   = acc[i][j][3];
        }
    }
    __syncthreads();

    for (int idx = tid; idx < 21 * KP; idx += 256) {
        int bl = idx / KP, j = idx - bl * KP;
        int b = bstart + bl;
        if (b < B) {
            float tv = 0.0f;
            #pragma unroll
            for (int c = 0; c < 6; c++)
                tv += tanhf(Cs[(bl * 6 + c) * 97 + j] + b1s[c]) * w2s[c];
            g_T[b * KP + j] = tv;
        }
    }
}

// ===========================================================================
// repack_t: g_T -> Trec (identity layout), per 128-b tile
// ===========================================================================
__global__ void repack_t_kernel(int B) {
    int rr = blockIdx.x * 256 + threadIdx.x;
    int mtile = blockIdx.y;
    int lane = rr & 31;
    int rest = rr >> 5;
    int s    = rest % NS;
    int nf   = rest / NS;
    int b  = mtile * 128 + nf * 8 + (lane >> 2);
    int k0 = s * 16 + 2 * (lane & 3);
    uint4 v = make_uint4(0, 0, 0, 0);
    if (b < B) {
        const float* p = g_T + (size_t)b * KP + k0;
        v = pack_rec(p[0], p[1], p[8], p[9]);
    }
    g_Trec[mtile * B_RECS + rr] = v;
}

// ===========================================================================
// GEMM2 fused: H[n][b] = tanh(A·T + b2); emits g_Arec records directly
// (one block == one fc m-tile of 128 b's)
// ===========================================================================
__global__ void __launch_bounds__(256, 2)
gemm2_kernel(const float* __restrict__ b2, int B) {
    extern __shared__ char sm[];
    uint4* Af = (uint4*)sm;
    uint4* Bf = (uint4*)sm + AG_RECS;
    float* Hs = (float*)sm;                 // reused: [128 b][97]
    const int tid = threadIdx.x;
    const int wid = tid >> 5, lane = tid & 31;
    const int b0 = blockIdx.x * 128;

    {
        const u32 af = smem_u32(Af), bf = smem_u32(Bf);
        const uint4* Bsrc = g_Trec + (size_t)blockIdx.x * B_RECS;
        #pragma unroll
        for (int r = 0; r < AG_RECS / 256; r++)
            cp16(af + (r * 256 + tid) * 16, g_AGrec + r * 256 + tid);
        #pragma unroll
        for (int r = 0; r < B_RECS / 256; r++)
            cp16(bf + (r * 256 + tid) * 16, Bsrc + r * 256 + tid);
        asm volatile("cp.async.commit_group;");
        asm volatile("cp.async.wait_group 0;" ::: "memory");
    }
    __syncthreads();

    const int mf0 = (wid & 1) * 3;
    const int nf0 = (wid >> 1) * 4;

    float acc[3][4][4];
    #pragma unroll
    for (int i = 0; i < 3; i++)
        #pragma unroll
        for (int j = 0; j < 4; j++)
            #pragma unroll
            for (int c = 0; c < 4; c++) acc[i][j][c] = 0.0f;

    #pragma unroll
    for (int s = 0; s < NS; s++) {
        uint4 ar0[3], ar1[3];
        #pragma unroll
        for (int i = 0; i < 3; i++) {
            int mf = mf0 + i;
            ar0[i] = Af[((mf * NS + s) * 2 + 0) * 32 + lane];
            ar1[i] = Af[((mf * NS + s) * 2 + 1) * 32 + lane];
        }
        #pragma unroll
        for (int j = 0; j < 4; j++) {
            uint4 br = Bf[((nf0 + j) * NS + s) * 32 + lane];
            #pragma unroll
            for (int i = 0; i < 3; i++) {
                mma_bf16(acc[i][j][0], acc[i][j][1], acc[i][j][2], acc[i][j][3],
                         ar0[i].x, ar1[i].x, ar0[i].y, ar1[i].y, br.x, br.y);
                mma_bf16(acc[i][j][0], acc[i][j][1], acc[i][j][2], acc[i][j][3],
                         ar0[i].x, ar1[i].x, ar0[i].y, ar1[i].y, br.z, br.w);
                mma_bf16(acc[i][j][0], acc[i][j][1], acc[i][j][2], acc[i][j][3],
                         ar0[i].z, ar1[i].z, ar0[i].w, ar1[i].w, br.x, br.y);
            }
        }
    }

    __syncthreads();   // staging smem dead -> reuse as Hs

    const float b2v = b2[0];
    const int g = lane >> 2, t = lane & 3;
    #pragma unroll
    for (int j = 0; j < 4; j++) {
        int bcol = (nf0 + j) * 8 + 2 * t;    // local b
        #pragma unroll
        for (int i = 0; i < 3; i++) {
            int row = (mf0 + i) * 16 + g;    // node index
            Hs[bcol * 97 + row]           = tanhf(acc[i][j][0] + b2v);
            Hs[(bcol + 1) * 97 + row]     = tanhf(acc[i][j][1] + b2v);
            Hs[bcol * 97 + row + 8]       = tanhf(acc[i][j][2] + b2v);
            Hs[(bcol + 1) * 97 + row + 8] = tanhf(acc[i][j][3] + b2v);
        }
    }
    __syncthreads();

    // Emit fc A-records directly
    for (int r = tid; r < A_RECS; r += 256) {
        int lane2 = r & 31;
        int rc    = (r >> 5) & 1;
        int rest  = r >> 6;
        int s     = rest % NS;
        int mf    = rest / NS;
        int ml = mf * 16 + rc * 8 + (lane2 >> 2);   // local b
        int k0 = s * 16 + 2 * (lane2 & 3);
        uint4 v = make_uint4(0, 0, 0, 0);
        if (b0 + ml < B) {
            const float* p = Hs + ml * 97 + k0;
            v = pack_rec(p[0], p[1], p[8], p[9]);
        }
        g_Arec[blockIdx.x * A_RECS + r] = v;
    }
}

// ===========================================================================
// FC GEMM — permuted STG.128 epilogue
// ===========================================================================
#define FC_SMEM ((A_RECS + B_RECS) * 16)  // 98304

__global__ void __launch_bounds__(256, 2)
fc_mma_kernel(const float* __restrict__ bfc, float* __restrict__ out, int B) {
    extern __shared__ char sm[];
    uint4* Af = (uint4*)sm;
    uint4* Bf = (uint4*)sm + A_RECS;

    const int tid  = threadIdx.x;
    const int wid  = tid >> 5;
    const int lane = tid & 31;
    const int m0   = blockIdx.y * 128;
    const int n0   = blockIdx.x * 128;

    {
        const u32 af = smem_u32(Af);
        const u32 bf = smem_u32(Bf);
        const uint4* Asrc = g_Arec + (size_t)blockIdx.y * A_RECS;
        const uint4* Bsrc = g_Brec + (size_t)blockIdx.x * B_RECS;
        #pragma unroll
        for (int r = 0; r < A_RECS / 256; r++)
            cp16(af + (r * 256 + tid) * 16, Asrc + r * 256 + tid);
        #pragma unroll
        for (int r = 0; r < B_RECS / 256; r++)
            cp16(bf + (r * 256 + tid) * 16, Bsrc + r * 256 + tid);
        asm volatile("cp.async.commit_group;");
        asm volatile("cp.async.wait_group 0;" ::: "memory");
    }
    __syncthreads();

    const int wm = wid & 3;
    const int wn = wid >> 2;
    const int mf0 = wm * 2;
    const int nf0 = wn * 8;

    float acc[2][8][4];
    #pragma unroll
    for (int i = 0; i < 2; i++)
        #pragma unroll
        for (int j = 0; j < 8; j++)
            #pragma unroll
            for (int c = 0; c < 4; c++) acc[i][j][c] = 0.0f;

    #pragma unroll
    for (int s = 0; s < NS; s++) {
        uint4 ar0[2], ar1[2];
        #pragma unroll
        for (int i = 0; i < 2; i++) {
            int mf = mf0 + i;
            ar0[i] = Af[((mf * NS + s) * 2 + 0) * 32 + lane];
            ar1[i] = Af[((mf * NS + s) * 2 + 1) * 32 + lane];
        }
        #pragma unroll
        for (int j = 0; j < 8; j++) {
            uint4 br = Bf[((nf0 + j) * NS + s) * 32 + lane];
            #pragma unroll
            for (int i = 0; i < 2; i++) {
                mma_bf16(acc[i][j][0], acc[i][j][1], acc[i][j][2], acc[i][j][3],
                         ar0[i].x, ar1[i].x, ar0[i].y, ar1[i].y, br.x, br.y);
                mma_bf16(acc[i][j][0], acc[i][j][1], acc[i][j][2], acc[i][j][3],
                         ar0[i].x, ar1[i].x, ar0[i].y, ar1[i].y, br.z, br.w);
                mma_bf16(acc[i][j][0], acc[i][j][1], acc[i][j][2], acc[i][j][3],
                         ar0[i].z, ar1[i].z, ar0[i].w, ar1[i].w, br.x, br.y);
            }
        }
    }

    // ---- Epilogue: permuted layout -> float4 stores ----
    const int g = lane >> 2, t = lane & 3;
    #pragma unroll
    for (int u = 0; u < 4; u++) {
        const int j0 = 2 * u, j1 = 2 * u + 1;
        const int nbase = n0 + 64 * wn + 16 * u + 4 * t;
        float4 bz = *(const float4*)(bfc + nbase);
        #pragma unroll
        for (int i = 0; i < 2; i++) {
            int mr0 = m0 + (mf0 + i) * 16 + g;
            if (mr0 < B) {
                float4 v = make_float4(acc[i][j0][0] + bz.x, acc[i][j0][1] + bz.y,
                                       acc[i][j1][0] + bz.z, acc[i][j1][1] + bz.w);
                *(float4*)(out + (size_t)mr0 * NOUT + nbase) = v;
            }
            int mr1 = mr0 + 8;
            if (mr1 < B) {
                float4 v = make_float4(acc[i][j0][2] + bz.x, acc[i][j0][3] + bz.y,
                                       acc[i][j1][2] + bz.z, acc[i][j1][3] + bz.w);
                *(float4*)(out + (size_t)mr1 * NOUT + nbase) = v;
            }
        }
    }
}

// ===========================================================================
// Launch
// ===========================================================================
extern "C" void kernel_launch(void* const* d_in, const int* in_sizes, int n_in,
                              void* d_out, int out_size) {
    const float* feature = (const float*)d_in[0];
    const int*   ei      = (const int*)  d_in[1];
    const float* ew      = (const float*)d_in[2];
    const float* W1      = (const float*)d_in[3];
    const float* b1      = (const float*)d_in[4];
    const float* W2      = (const float*)d_in[5];
    const float* b2      = (const float*)d_in[6];
    const float* Wfc     = (const float*)d_in[7];
    const float* bfc     = (const float*)d_in[8];
    float*       out     = (float*)d_out;

    const int B = in_sizes[0] / (NNODE * 3);
    const int E = in_sizes[1] / 2;
    const int nmt  = (B + 127) / 128;
    const int nt21 = (B + 20) / 21;

    cudaFuncSetAttribute(xz_kernel,    cudaFuncAttributeMaxDynamicSharedMemorySize, XZ_SMEM);
    cudaFuncSetAttribute(gemm1_kernel, cudaFuncAttributeMaxDynamicSharedMemorySize, G_SMEM);
    cudaFuncSetAttribute(gemm2_kernel, cudaFuncAttributeMaxDynamicSharedMemorySize, G_SMEM);
    cudaFuncSetAttribute(fc_mma_kernel,cudaFuncAttributeMaxDynamicSharedMemorySize, FC_SMEM);

    build_graph_kernel<<<1, 256>>>(ei, ew, E);
    repack_ag_kernel<<<(AG_RECS + 255) / 256, 256>>>();

    { dim3 gb(B_RECS / 256, NNT); repack_b_kernel<<<gb, 256>>>(Wfc); }

    xz_kernel<<<nt21, 256, XZ_SMEM>>>(feature, W1, B);
    gemm1_kernel<<<nt21, 256, G_SMEM>>>(b1, W2, B);
    { dim3 gt(B_RECS / 256, nmt); repack_t_kernel<<<gt, 256>>>(B); }
    gemm2_kernel<<<nmt, 256, G_SMEM>>>(b2, B);

    dim3 grid(NNT, nmt);
    fc_mma_kernel<<<grid, 256, FC_SMEM>>>(bfc, out, B);
}